// round 15
// baseline (speedup 1.0000x reference)
#include <cuda_runtime.h>
#include <cuda_fp16.h>
#include <mma.h>
#include <cstdint>

using namespace nvcuda;

#define N_NODES 8192
#define D_IN    512
#define D_OUT   256
#define NCHUNK  128
#define M_CTA   64

// attn smem layout (bytes)
#define A_BUF   9216             // 64 x 72 halves
#define OFF_B   27648            // 3 A slots
#define B_BUF   33792            // 64 x 264 halves
#define OFF_ADJ 129024           // 3 B slots end
#define ADJ_BUF 17408            // 64 rows x 272B (256B data + 16B pad)
#define OFF_Q   198656           // 4 adj slots end
#define OFF_Z   200704           // 4 x 512B Q ring end
#define SMEM_ATTN 200960
// epilogue overlay: Sh fp32 64 x 260 = 66560 B at offset 0

// ---------------- scratch (static device arrays; no allocation) ----------------
__device__ float                 g_s[N_NODES];
__device__ __align__(16) float2  g_Qq[N_NODES];                 // (e^{t_j}, e^{0.2 t_j})
__device__ __align__(16) __half  g_Bh[(size_t)N_NODES * D_OUT]; // fp16 Wh

// ---------------- helpers ----------------
__device__ __forceinline__ void cpa16(void* dst, const void* src) {
    unsigned d = (unsigned)__cvta_generic_to_shared(dst);
    asm volatile("cp.async.cg.shared.global [%0], [%1], 16;\n" :: "r"(d), "l"(src));
}
#define CP_COMMIT() asm volatile("cp.async.commit_group;\n")

__device__ __forceinline__ void bar_sync(int id, int cnt) {
    asm volatile("bar.sync %0, %1;" :: "r"(id), "r"(cnt) : "memory");
}

// ---------------- Wh GEMM + fused epilogue (Bh fp16, s, Qq); weight converted inline ----------------
#define SMEM_GEMM 66560
__global__ __launch_bounds__(256) void gemm_wh_kernel(const float* __restrict__ input,
                                                      const float* __restrict__ weight,
                                                      const float* __restrict__ a) {
    extern __shared__ __align__(16) char gsm[];
    __half* As = (__half*)gsm;                 // 64 x 80
    __half* Bs = (__half*)(gsm + 10240);       // 64 x 272
    float*  Sh = (float*)gsm;                  // epilogue overlay 64 x 260
    int tid  = threadIdx.x;
    int warp = tid >> 5, lane = tid & 31;
    int grow = blockIdx.x * 64;
    int m0 = (warp >> 1) * 16;
    int n0 = (warp & 1) * 128;

    wmma::fragment<wmma::accumulator, 16, 16, 16, float> acc[8];
#pragma unroll
    for (int i = 0; i < 8; i++) wmma::fill_fragment(acc[i], 0.0f);

    for (int kc = 0; kc < D_IN; kc += 64) {
        __syncthreads();
#pragma unroll
        for (int i = tid; i < 1024; i += 256) {
            int row = i >> 4, q = i & 15;
            float4 f = *(const float4*)(input + (size_t)(grow + row) * D_IN + kc + q * 4);
            *(__half2*)(As + row * 80 + q * 4)     = __floats2half2_rn(f.x, f.y);
            *(__half2*)(As + row * 80 + q * 4 + 2) = __floats2half2_rn(f.z, f.w);
        }
#pragma unroll
        for (int i = tid; i < 2048; i += 256) {
            int row = i >> 5, q = i & 31;
            const float* wp = weight + (size_t)(kc + row) * D_OUT + q * 8;
            float4 f0 = *(const float4*)wp;
            float4 f1 = *(const float4*)(wp + 4);
            __half* d = Bs + row * 272 + q * 8;
            *(__half2*)(d)     = __floats2half2_rn(f0.x, f0.y);
            *(__half2*)(d + 2) = __floats2half2_rn(f0.z, f0.w);
            *(__half2*)(d + 4) = __floats2half2_rn(f1.x, f1.y);
            *(__half2*)(d + 6) = __floats2half2_rn(f1.z, f1.w);
        }
        __syncthreads();
#pragma unroll
        for (int kk = 0; kk < 4; kk++) {
            wmma::fragment<wmma::matrix_a, 16, 16, 16, __half, wmma::row_major> af;
            wmma::load_matrix_sync(af, As + m0 * 80 + kk * 16, 80);
#pragma unroll
            for (int nt = 0; nt < 8; nt++) {
                wmma::fragment<wmma::matrix_b, 16, 16, 16, __half, wmma::row_major> bf;
                wmma::load_matrix_sync(bf, Bs + kk * 16 * 272 + n0 + nt * 16, 272);
                wmma::mma_sync(acc[nt], af, bf, acc[nt]);
            }
        }
    }

    __syncthreads();
#pragma unroll
    for (int nt = 0; nt < 8; nt++)
        wmma::store_matrix_sync(Sh + m0 * 260 + n0 + nt * 16, acc[nt], 260, wmma::mem_row_major);
    __syncthreads();

#pragma unroll 4
    for (int r = 0; r < 64; r++)
        g_Bh[(size_t)(grow + r) * D_OUT + tid] = __float2half(Sh[r * 260 + tid]);

#pragma unroll
    for (int i = 0; i < 8; i++) {
        int row = warp * 8 + i;
        float s = 0.f, t = 0.f;
#pragma unroll
        for (int k = lane; k < 256; k += 32) {
            float w = Sh[row * 260 + k];
            s += w * a[k];
            t += w * a[k + 256];
        }
#pragma unroll
        for (int off = 16; off; off >>= 1) {
            s += __shfl_down_sync(0xffffffffu, s, off);
            t += __shfl_down_sync(0xffffffffu, t, off);
        }
        if (lane == 0) {
            g_s[grow + row]  = s;
            g_Qq[grow + row] = make_float2(expf(t), expf(0.2f * t));
        }
    }
}

// ---------------- attention: 8 consumer + 8 producer warps; adj staged via cp.async ----------------

// build 16 fp16 attention weights for (row, cols pq*16..+16); adj read from smem
__device__ __forceinline__ float build16(__half* Ab, const float2* qb, const char* arow,
                                         float P, float p, int row, int pq) {
    float z = 0.f;
    __align__(16) __half h[16];
#pragma unroll
    for (int q = 0; q < 4; q++) {
        int4 a = *(const int4*)(arow + q * 16);
        float2 q0 = qb[q * 4 + 0], q1 = qb[q * 4 + 1];
        float2 q2 = qb[q * 4 + 2], q3 = qb[q * 4 + 3];
        // exp(leaky(s+t)) = max(e^s e^t, e^{0.2s} e^{0.2t})
        float v0 = fmaxf(P * q0.x, p * q0.y); v0 = a.x ? v0 : 0.f;
        float v1 = fmaxf(P * q1.x, p * q1.y); v1 = a.y ? v1 : 0.f;
        float v2 = fmaxf(P * q2.x, p * q2.y); v2 = a.z ? v2 : 0.f;
        float v3 = fmaxf(P * q3.x, p * q3.y); v3 = a.w ? v3 : 0.f;
        z += (v0 + v1) + (v2 + v3);
        h[q * 4 + 0] = __float2half(v0);
        h[q * 4 + 1] = __float2half(v1);
        h[q * 4 + 2] = __float2half(v2);
        h[q * 4 + 3] = __float2half(v3);
    }
    uint4* d = (uint4*)(Ab + row * 72 + pq * 16);
    d[0] = *(const uint4*)&h[0];
    d[1] = *(const uint4*)&h[8];
    return z;
}

// stage group G(c): B(c)->slot c%3, adj(c+1)->aslot (c+1)&3, Q(c+2)->ring (c+2)&3
__device__ __forceinline__ void issueG(char* smem, int c, int ptid, const int* adjbase) {
    const char* bs = (const char*)g_Bh + (size_t)c * 32768;
    char* bd = smem + OFF_B + (c % 3) * B_BUF;
#pragma unroll
    for (int i = 0; i < 8; i++) {
        int idx = ptid + i * 256;
        int r = idx >> 5, sg = idx & 31;
        cpa16(bd + r * 528 + sg * 16, bs + (size_t)r * 512 + sg * 16);
    }
    if (c + 1 < NCHUNK) {
        const char* as = (const char*)(adjbase + (c + 1) * 64);
        char* ad = smem + OFF_ADJ + ((c + 1) & 3) * ADJ_BUF;
#pragma unroll
        for (int i = 0; i < 4; i++) {
            int idx = ptid + i * 256;
            int r = idx >> 4, sg = idx & 15;
            cpa16(ad + r * 272 + sg * 16, as + (size_t)r * 32768 + sg * 16);
        }
    }
    if (ptid < 32 && c + 2 < NCHUNK)
        cpa16(smem + OFF_Q + ((c + 2) & 3) * 512 + ptid * 16,
              (const char*)g_Qq + (size_t)(c + 2) * 512 + ptid * 16);
    CP_COMMIT();
}

__device__ __forceinline__ void prod_iter(int c, char* smem, const int* adjbase,
                                          int ptid, int prow, int pq,
                                          float P, float p, float& zacc, float* Zs) {
    if (c + 1 < NCHUNK) {
        issueG(smem, c + 1, ptid, adjbase);                      // B(c+1), adj(c+2), Q(c+3)
        asm volatile("cp.async.wait_group 1;" ::: "memory");     // G(c) landed: B(c), adj(c+1), Q(c+2)
    } else {
        asm volatile("cp.async.wait_group 0;" ::: "memory");
    }
    // build A(c) into slot c%3; adj(c) from aslot c&3 (landed >=1 bar ago), Q(c) from ring
    const char* arow = smem + OFF_ADJ + (c & 3) * ADJ_BUF + prow * 272 + pq * 64;
    zacc += build16((__half*)(smem + (c % 3) * A_BUF),
                    (const float2*)(smem + OFF_Q + (c & 3) * 512) + pq * 16,
                    arow, P, p, prow, pq);
    if (c == NCHUNK - 1) {
        float z = zacc;
        z += __shfl_xor_sync(0xffffffffu, z, 1);
        z += __shfl_xor_sync(0xffffffffu, z, 2);
        if (pq == 0) Zs[prow] = (z > 0.f) ? 1.f / z : 0.f;
    }
    bar_sync(1, 512);                        // rendezvous: drains producer STS
}

__global__ __launch_bounds__(512, 1) void attn_kernel(const int* __restrict__ adj,
                                                      float* __restrict__ out) {
    extern __shared__ __align__(16) char smem[];
    int tid  = threadIdx.x;
    int warp = tid >> 5;
    int grow = blockIdx.x * M_CTA;

    if (warp >= 8) {
        // ======================= PRODUCERS (warps 8-15) =======================
        int ptid = tid - 256;          // 0..255
        int prow = ptid >> 2;          // 0..63
        int pq   = ptid & 3;           // 16-col group
        float* Zs = (float*)(smem + OFF_Z);
        const int* adjbase = adj + (size_t)grow * N_NODES;

        // preamble P0: B(0)->slot0, adj(0)->aslot0, adj(1)->aslot1, Q(0..2)
        {
            const char* bs = (const char*)g_Bh;
            char* bd = smem + OFF_B;
#pragma unroll
            for (int i = 0; i < 8; i++) {
                int idx = ptid + i * 256;
                int r = idx >> 5, sg = idx & 31;
                cpa16(bd + r * 528 + sg * 16, bs + (size_t)r * 512 + sg * 16);
            }
#pragma unroll
            for (int cc = 0; cc < 2; cc++) {
                const char* as = (const char*)(adjbase + cc * 64);
                char* ad = smem + OFF_ADJ + cc * ADJ_BUF;
#pragma unroll
                for (int i = 0; i < 4; i++) {
                    int idx = ptid + i * 256;
                    int r = idx >> 4, sg = idx & 15;
                    cpa16(ad + r * 272 + sg * 16, as + (size_t)r * 32768 + sg * 16);
                }
            }
            if (ptid < 32) {
                cpa16(smem + OFF_Q + ptid * 16,        (const char*)g_Qq + ptid * 16);
                cpa16(smem + OFF_Q + 512 + ptid * 16,  (const char*)g_Qq + 512 + ptid * 16);
                cpa16(smem + OFF_Q + 1024 + ptid * 16, (const char*)g_Qq + 1024 + ptid * 16);
            }
            CP_COMMIT();
        }

        float s = g_s[grow + prow];
        float P = expf(s), p = expf(0.2f * s);
        float zacc = 0.f;

        asm volatile("cp.async.wait_group 0;" ::: "memory");
        bar_sync(8, 256);                                        // producer-local visibility

        for (int c = 0; c < NCHUNK; c++)
            prod_iter(c, smem, adjbase, ptid, prow, pq, P, p, zacc, Zs);
    } else {
        // ======================= CONSUMERS (warps 0-7): m32 x n64 each =======================
        int m0 = (warp & 1) * 32;
        int n0 = (warp >> 1) * 64;

        wmma::fragment<wmma::accumulator, 16, 16, 16, float> acc[2][4];
#pragma unroll
        for (int mi = 0; mi < 2; mi++)
#pragma unroll
            for (int ni = 0; ni < 4; ni++) wmma::fill_fragment(acc[mi][ni], 0.f);

        for (int c = 0; c < NCHUNK; c++) {
            bar_sync(1, 512);                                   // chunk c ready
            const __half* Ab = (const __half*)(smem + (c % 3) * A_BUF);
            const __half* Bb = (const __half*)(smem + OFF_B + (c % 3) * B_BUF);
#pragma unroll
            for (int kk = 0; kk < 4; kk++) {
                wmma::fragment<wmma::matrix_a, 16, 16, 16, __half, wmma::row_major> af0, af1;
                wmma::load_matrix_sync(af0, Ab + (m0)      * 72 + kk * 16, 72);
                wmma::load_matrix_sync(af1, Ab + (m0 + 16) * 72 + kk * 16, 72);
#pragma unroll
                for (int ni = 0; ni < 4; ni++) {
                    wmma::fragment<wmma::matrix_b, 16, 16, 16, __half, wmma::row_major> bf;
                    wmma::load_matrix_sync(bf, Bb + kk * 16 * 264 + n0 + ni * 16, 264);
                    wmma::mma_sync(acc[0][ni], af0, bf, acc[0][ni]);
                    wmma::mma_sync(acc[1][ni], af1, bf, acc[1][ni]);
                }
            }
        }

        // ---- epilogue: out = elu( numerator / Z ) ----
        bar_sync(7, 256);                                      // consumers drained
        float* Sh = (float*)smem;                              // 64 x 260 fp32 overlay
#pragma unroll
        for (int mi = 0; mi < 2; mi++)
#pragma unroll
            for (int ni = 0; ni < 4; ni++)
                wmma::store_matrix_sync(Sh + (m0 + mi * 16) * 260 + n0 + ni * 16,
                                        acc[mi][ni], 260, wmma::mem_row_major);
        bar_sync(7, 256);
        float* Zsf = (float*)(smem + OFF_Z);
#pragma unroll 4
        for (int r = 0; r < 64; r++) {
            float val = Sh[r * 260 + tid] * Zsf[r];
            out[(size_t)(grow + r) * D_OUT + tid] = (val > 0.f) ? val : expm1f(val);
        }
    }
}

// ---------------- launch ----------------
extern "C" void kernel_launch(void* const* d_in, const int* in_sizes, int n_in,
                              void* d_out, int out_size) {
    const float* input  = nullptr;
    const int*   adj    = nullptr;
    const float* weight = nullptr;
    const float* a      = nullptr;
    for (int i = 0; i < n_in; i++) {
        switch (in_sizes[i]) {
            case N_NODES * D_IN:    input  = (const float*)d_in[i]; break;
            case 67108864:          adj    = (const int*)d_in[i];   break;
            case D_IN * D_OUT:      weight = (const float*)d_in[i]; break;
            case 2 * D_OUT:         a      = (const float*)d_in[i]; break;
        }
    }

    cudaFuncSetAttribute(gemm_wh_kernel, cudaFuncAttributeMaxDynamicSharedMemorySize, SMEM_GEMM);
    cudaFuncSetAttribute(attn_kernel,    cudaFuncAttributeMaxDynamicSharedMemorySize, SMEM_ATTN);

    gemm_wh_kernel<<<N_NODES / 64, 256, SMEM_GEMM>>>(input, weight, a);
    attn_kernel<<<N_NODES / M_CTA, 512, SMEM_ATTN>>>(adj, (float*)d_out);
}

// round 16
// speedup vs baseline: 1.2378x; 1.2378x over previous
#include <cuda_runtime.h>
#include <cuda_fp16.h>
#include <mma.h>
#include <cstdint>

using namespace nvcuda;

#define N_NODES 8192
#define D_IN    512
#define D_OUT   256
#define NCHUNK  128
#define M_CTA   64

// attn smem layout (bytes)
#define A_BUF   9216             // 64 x 72 halves
#define OFF_B   27648            // 3 A slots
#define B_BUF   33792            // 64 x 264 halves
#define OFF_ADJ 129024           // 3 B slots end
#define ADJ_BUF 17408            // 64 rows x 272B (256B data + 16B pad)
#define OFF_Q   198656           // 4 adj slots end
#define OFF_Z   200704           // 4 x 512B Q ring end
#define SMEM_ATTN 200960
// epilogue overlay: Sh fp32 64 x 260 = 66560 B at offset 0

// ---------------- scratch (static device arrays; no allocation) ----------------
__device__ float                 g_s[N_NODES];
__device__ __align__(16) float2  g_Qq[N_NODES];                 // (e^{t_j}, e^{0.2 t_j})
__device__ __align__(16) __half  g_Bh[(size_t)N_NODES * D_OUT]; // fp16 Wh

// ---------------- helpers ----------------
__device__ __forceinline__ void cpa16(void* dst, const void* src) {
    unsigned d = (unsigned)__cvta_generic_to_shared(dst);
    asm volatile("cp.async.cg.shared.global [%0], [%1], 16;\n" :: "r"(d), "l"(src));
}
#define CP_COMMIT() asm volatile("cp.async.commit_group;\n")

__device__ __forceinline__ void bar_sync(int id, int cnt) {
    asm volatile("bar.sync %0, %1;" :: "r"(id), "r"(cnt) : "memory");
}

// ---------------- Wh GEMM + fused epilogue (Bh fp16, s, Qq); weight converted inline ----------------
#define SMEM_GEMM 66560
__global__ __launch_bounds__(256) void gemm_wh_kernel(const float* __restrict__ input,
                                                      const float* __restrict__ weight,
                                                      const float* __restrict__ a) {
    extern __shared__ __align__(16) char gsm[];
    __half* As = (__half*)gsm;                 // 64 x 80
    __half* Bs = (__half*)(gsm + 10240);       // 64 x 272
    float*  Sh = (float*)gsm;                  // epilogue overlay 64 x 260
    int tid  = threadIdx.x;
    int warp = tid >> 5, lane = tid & 31;
    int grow = blockIdx.x * 64;
    int m0 = (warp >> 1) * 16;
    int n0 = (warp & 1) * 128;

    wmma::fragment<wmma::accumulator, 16, 16, 16, float> acc[8];
#pragma unroll
    for (int i = 0; i < 8; i++) wmma::fill_fragment(acc[i], 0.0f);

    for (int kc = 0; kc < D_IN; kc += 64) {
        __syncthreads();
#pragma unroll
        for (int i = tid; i < 1024; i += 256) {
            int row = i >> 4, q = i & 15;
            float4 f = *(const float4*)(input + (size_t)(grow + row) * D_IN + kc + q * 4);
            *(__half2*)(As + row * 80 + q * 4)     = __floats2half2_rn(f.x, f.y);
            *(__half2*)(As + row * 80 + q * 4 + 2) = __floats2half2_rn(f.z, f.w);
        }
#pragma unroll
        for (int i = tid; i < 2048; i += 256) {
            int row = i >> 5, q = i & 31;
            const float* wp = weight + (size_t)(kc + row) * D_OUT + q * 8;
            float4 f0 = *(const float4*)wp;
            float4 f1 = *(const float4*)(wp + 4);
            __half* d = Bs + row * 272 + q * 8;
            *(__half2*)(d)     = __floats2half2_rn(f0.x, f0.y);
            *(__half2*)(d + 2) = __floats2half2_rn(f0.z, f0.w);
            *(__half2*)(d + 4) = __floats2half2_rn(f1.x, f1.y);
            *(__half2*)(d + 6) = __floats2half2_rn(f1.z, f1.w);
        }
        __syncthreads();
#pragma unroll
        for (int kk = 0; kk < 4; kk++) {
            wmma::fragment<wmma::matrix_a, 16, 16, 16, __half, wmma::row_major> af;
            wmma::load_matrix_sync(af, As + m0 * 80 + kk * 16, 80);
#pragma unroll
            for (int nt = 0; nt < 8; nt++) {
                wmma::fragment<wmma::matrix_b, 16, 16, 16, __half, wmma::row_major> bf;
                wmma::load_matrix_sync(bf, Bs + kk * 16 * 272 + n0 + nt * 16, 272);
                wmma::mma_sync(acc[nt], af, bf, acc[nt]);
            }
        }
    }

    __syncthreads();
#pragma unroll
    for (int nt = 0; nt < 8; nt++)
        wmma::store_matrix_sync(Sh + m0 * 260 + n0 + nt * 16, acc[nt], 260, wmma::mem_row_major);
    __syncthreads();

#pragma unroll 4
    for (int r = 0; r < 64; r++)
        g_Bh[(size_t)(grow + r) * D_OUT + tid] = __float2half(Sh[r * 260 + tid]);

#pragma unroll
    for (int i = 0; i < 8; i++) {
        int row = warp * 8 + i;
        float s = 0.f, t = 0.f;
#pragma unroll
        for (int k = lane; k < 256; k += 32) {
            float w = Sh[row * 260 + k];
            s += w * a[k];
            t += w * a[k + 256];
        }
#pragma unroll
        for (int off = 16; off; off >>= 1) {
            s += __shfl_down_sync(0xffffffffu, s, off);
            t += __shfl_down_sync(0xffffffffu, t, off);
        }
        if (lane == 0) {
            g_s[grow + row]  = s;
            g_Qq[grow + row] = make_float2(expf(t), expf(0.2f * t));
        }
    }
}

// ---------------- attention: warp-specialized; adj staged via cp.async ring ----------------

// build 32 fp16 attention weights for (row, cols phalf*32..+32); adj+Q from smem
__device__ __forceinline__ float build32(__half* Ab, const float4* qv, const char* arow,
                                         float P, float p, int row, int phalf) {
    float z0 = 0.f, z1 = 0.f, z2 = 0.f, z3 = 0.f;   // 4-way to break FADD chain
    __align__(16) __half h[32];
#pragma unroll
    for (int q = 0; q < 8; q++) {
        int4 a = *(const int4*)(arow + q * 16);
        float4 qa = qv[q * 2];          // (q0x,q0y,q1x,q1y)
        float4 qb = qv[q * 2 + 1];      // (q2x,q2y,q3x,q3y)
        // exp(leaky(s+t)) = max(e^s e^t, e^{0.2s} e^{0.2t})
        float v0 = fmaxf(P * qa.x, p * qa.y); v0 = a.x ? v0 : 0.f;
        float v1 = fmaxf(P * qa.z, p * qa.w); v1 = a.y ? v1 : 0.f;
        float v2 = fmaxf(P * qb.x, p * qb.y); v2 = a.z ? v2 : 0.f;
        float v3 = fmaxf(P * qb.z, p * qb.w); v3 = a.w ? v3 : 0.f;
        z0 += v0; z1 += v1; z2 += v2; z3 += v3;
        h[q * 4 + 0] = __float2half(v0);
        h[q * 4 + 1] = __float2half(v1);
        h[q * 4 + 2] = __float2half(v2);
        h[q * 4 + 3] = __float2half(v3);
    }
    uint4* d = (uint4*)(Ab + row * 72 + phalf * 32);
    d[0] = *(const uint4*)&h[0];
    d[1] = *(const uint4*)&h[8];
    d[2] = *(const uint4*)&h[16];
    d[3] = *(const uint4*)&h[24];
    return (z0 + z1) + (z2 + z3);
}

// stage group G(c): adj(c+1)->aslot (c+1)&3, Q(c+2)->ring (c+2)&3, B(c)->slot c%3
__device__ __forceinline__ void issueG(char* smem, int c, int ptid, const int* adjbase) {
    if (c + 1 < NCHUNK) {
        const char* as = (const char*)(adjbase + (c + 1) * 64);
        char* ad = smem + OFF_ADJ + ((c + 1) & 3) * ADJ_BUF;
#pragma unroll
        for (int i = 0; i < 8; i++) {
            int idx = ptid + i * 128;
            int r = idx >> 4, sg = idx & 15;
            cpa16(ad + r * 272 + sg * 16, as + (size_t)r * 32768 + sg * 16);
        }
    }
    if (ptid < 32 && c + 2 < NCHUNK)
        cpa16(smem + OFF_Q + ((c + 2) & 3) * 512 + ptid * 16,
              (const char*)g_Qq + (size_t)(c + 2) * 512 + ptid * 16);
    {
        const char* bs = (const char*)g_Bh + (size_t)c * 32768;
        char* bd = smem + OFF_B + (c % 3) * B_BUF;
#pragma unroll
        for (int i = 0; i < 16; i++) {
            int idx = ptid + i * 128;
            int r = idx >> 5, sg = idx & 31;
            cpa16(bd + r * 528 + sg * 16, bs + (size_t)r * 512 + sg * 16);
        }
    }
    CP_COMMIT();
}

__device__ __forceinline__ void prod_iter(int c, char* smem, const int* adjbase,
                                          int ptid, int prow, int phalf,
                                          float P, float p, float& zacc, float* Zs) {
    // issue G(c+1) first: max flight time for B(c+1), adj(c+2), Q(c+3)
    if (c + 1 < NCHUNK) issueG(smem, c + 1, ptid, adjbase);
    // build A(c) BEFORE waiting: its deps (adj(c), Q(c)) landed >= 1 full iteration ago.
    // This overlaps G(c)'s residual cp.async flight (B(c)) with the ~500-cycle build.
    const char* arow = smem + OFF_ADJ + (c & 3) * ADJ_BUF + prow * 272 + phalf * 128;
    zacc += build32((__half*)(smem + (c % 3) * A_BUF),
                    (const float4*)(smem + OFF_Q + (c & 3) * 512) + phalf * 16,
                    arow, P, p, prow, phalf);
    if (c == NCHUNK - 1) {
        float z = zacc;
        z += __shfl_xor_sync(0xffffffffu, z, 1);
        if (phalf == 0) Zs[prow] = (z > 0.f) ? 1.f / z : 0.f;
    }
    // now guarantee G(c) (B(c), adj(c+1), Q(c+2)) landed before the rendezvous
    if (c + 1 < NCHUNK) { asm volatile("cp.async.wait_group 1;" ::: "memory"); }
    else                { asm volatile("cp.async.wait_group 0;" ::: "memory"); }
    bar_sync(1, 384);                        // rendezvous: drains producer STS
}

__global__ __launch_bounds__(384, 1) void attn_kernel(const int* __restrict__ adj,
                                                      float* __restrict__ out) {
    extern __shared__ __align__(16) char smem[];
    int tid  = threadIdx.x;
    int warp = tid >> 5;
    int grow = blockIdx.x * M_CTA;

    if (warp >= 8) {
        // ======================= PRODUCERS (warps 8-11) =======================
        int ptid  = tid - 256;          // 0..127
        int prow  = ptid >> 1;
        int phalf = ptid & 1;
        float* Zs = (float*)(smem + OFF_Z);
        const int* adjbase = adj + (size_t)grow * N_NODES;

        // preamble P0: B(0)->slot0, adj(0)->aslot0, adj(1)->aslot1, Q(0..2)
        {
            const char* bs = (const char*)g_Bh;
            char* bd = smem + OFF_B;
#pragma unroll
            for (int i = 0; i < 16; i++) {
                int idx = ptid + i * 128;
                int r = idx >> 5, sg = idx & 31;
                cpa16(bd + r * 528 + sg * 16, bs + (size_t)r * 512 + sg * 16);
            }
#pragma unroll
            for (int cc = 0; cc < 2; cc++) {
                const char* as = (const char*)(adjbase + cc * 64);
                char* ad = smem + OFF_ADJ + cc * ADJ_BUF;
#pragma unroll
                for (int i = 0; i < 8; i++) {
                    int idx = ptid + i * 128;
                    int r = idx >> 4, sg = idx & 15;
                    cpa16(ad + r * 272 + sg * 16, as + (size_t)r * 32768 + sg * 16);
                }
            }
            if (ptid < 32) {
                cpa16(smem + OFF_Q + ptid * 16,        (const char*)g_Qq + ptid * 16);
                cpa16(smem + OFF_Q + 512 + ptid * 16,  (const char*)g_Qq + 512 + ptid * 16);
                cpa16(smem + OFF_Q + 1024 + ptid * 16, (const char*)g_Qq + 1024 + ptid * 16);
            }
            CP_COMMIT();
        }

        float s = g_s[grow + prow];
        float P = expf(s), p = expf(0.2f * s);
        float zacc = 0.f;

        asm volatile("cp.async.wait_group 0;" ::: "memory");
        bar_sync(8, 128);                                        // producer-local visibility

        for (int c = 0; c < NCHUNK; c++)
            prod_iter(c, smem, adjbase, ptid, prow, phalf, P, p, zacc, Zs);
    } else {
        // ======================= CONSUMERS (warps 0-7): m32 x n64 each =======================
        int m0 = (warp & 1) * 32;
        int n0 = (warp >> 1) * 64;

        wmma::fragment<wmma::accumulator, 16, 16, 16, float> acc[2][4];
#pragma unroll
        for (int mi = 0; mi < 2; mi++)
#pragma unroll
            for (int ni = 0; ni < 4; ni++) wmma::fill_fragment(acc[mi][ni], 0.f);

        for (int c = 0; c < NCHUNK; c++) {
            bar_sync(1, 384);                                   // chunk c ready
            const __half* Ab = (const __half*)(smem + (c % 3) * A_BUF);
            const __half* Bb = (const __half*)(smem + OFF_B + (c % 3) * B_BUF);
#pragma unroll
            for (int kk = 0; kk < 4; kk++) {
                wmma::fragment<wmma::matrix_a, 16, 16, 16, __half, wmma::row_major> af0, af1;
                wmma::load_matrix_sync(af0, Ab + (m0)      * 72 + kk * 16, 72);
                wmma::load_matrix_sync(af1, Ab + (m0 + 16) * 72 + kk * 16, 72);
#pragma unroll
                for (int ni = 0; ni < 4; ni++) {
                    wmma::fragment<wmma::matrix_b, 16, 16, 16, __half, wmma::row_major> bf;
                    wmma::load_matrix_sync(bf, Bb + kk * 16 * 264 + n0 + ni * 16, 264);
                    wmma::mma_sync(acc[0][ni], af0, bf, acc[0][ni]);
                    wmma::mma_sync(acc[1][ni], af1, bf, acc[1][ni]);
                }
            }
        }

        // ---- epilogue: out = elu( numerator / Z ) ----
        bar_sync(7, 256);                                      // consumers drained
        float* Sh = (float*)smem;                              // 64 x 260 fp32 overlay
#pragma unroll
        for (int mi = 0; mi < 2; mi++)
#pragma unroll
            for (int ni = 0; ni < 4; ni++)
                wmma::store_matrix_sync(Sh + (m0 + mi * 16) * 260 + n0 + ni * 16,
                                        acc[mi][ni], 260, wmma::mem_row_major);
        bar_sync(7, 256);
        float* Zsf = (float*)(smem + OFF_Z);
#pragma unroll 4
        for (int r = 0; r < 64; r++) {
            float val = Sh[r * 260 + tid] * Zsf[r];
            out[(size_t)(grow + r) * D_OUT + tid] = (val > 0.f) ? val : expm1f(val);
        }
    }
}

// ---------------- launch ----------------
extern "C" void kernel_launch(void* const* d_in, const int* in_sizes, int n_in,
                              void* d_out, int out_size) {
    const float* input  = nullptr;
    const int*   adj    = nullptr;
    const float* weight = nullptr;
    const float* a      = nullptr;
    for (int i = 0; i < n_in; i++) {
        switch (in_sizes[i]) {
            case N_NODES * D_IN:    input  = (const float*)d_in[i]; break;
            case 67108864:          adj    = (const int*)d_in[i];   break;
            case D_IN * D_OUT:      weight = (const float*)d_in[i]; break;
            case 2 * D_OUT:         a      = (const float*)d_in[i]; break;
        }
    }

    cudaFuncSetAttribute(gemm_wh_kernel, cudaFuncAttributeMaxDynamicSharedMemorySize, SMEM_GEMM);
    cudaFuncSetAttribute(attn_kernel,    cudaFuncAttributeMaxDynamicSharedMemorySize, SMEM_ATTN);

    gemm_wh_kernel<<<N_NODES / 64, 256, SMEM_GEMM>>>(input, weight, a);
    attn_kernel<<<N_NODES / M_CTA, 384, SMEM_ATTN>>>(adj, (float*)d_out);
}